// round 2
// baseline (speedup 1.0000x reference)
#include <cuda_runtime.h>

#define NN 100000
#define NE 1000000
#define ND 64
#define ED 32
#define GD 32
#define HD 128
#define NG 64

typedef unsigned long long u64;

// ------------------------------ scratch ------------------------------------
__device__ int   g_is64e, g_is64n;
__device__ int   g_row[NE];
__device__ int   g_col[NE];
__device__ int   g_nb[NN];
__device__ float g_xa[NN * HD];   // x@mw1[0:64] + mb1
__device__ float g_S [NN * HD];   // sum_e w*h  (atomic)
__device__ float g_W [NN];        // sum_e w
__device__ float g_C [NN];        // count
__device__ float g_M [HD * HD];   // mw2 @ uw1[64:128]
__device__ float g_c2[HD];        // mb2 @ uw1[64:128]
__device__ float g_uu[NG * HD];   // u @ uw1[128:160] + ub1
__device__ float g_h2[NN * HD];   // relu(node pre-activation)

// --------------------------- f32x2 helpers ---------------------------------
__device__ __forceinline__ u64 pk2(float a) {
    u64 r; unsigned int ai = __float_as_uint(a);
    asm("mov.b64 %0, {%1, %1};" : "=l"(r) : "r"(ai));
    return r;
}
__device__ __forceinline__ void fma2(u64& d, u64 a, u64 b) {
    asm("fma.rn.f32x2 %0, %1, %2, %0;" : "+l"(d) : "l"(a), "l"(b));
}
__device__ __forceinline__ void up2(u64 v, float& lo, float& hi) {
    unsigned int l, h;
    asm("mov.b64 {%0, %1}, %2;" : "=r"(l), "=r"(h) : "l"(v));
    lo = __uint_as_float(l); hi = __uint_as_float(h);
}
__device__ __forceinline__ void red4(float* p, float a, float b, float c, float d) {
    asm volatile("red.global.add.v4.f32 [%0], {%1, %2, %3, %4};"
                 :: "l"(p), "f"(a), "f"(b), "f"(c), "f"(d) : "memory");
}

// ------------------------- dtype detect + convert --------------------------
// If data is int64 (little-endian), high 32-bit words are 0 (values < 1e5).
// Sample spread positions so sorted node_batch (leading zeros) can't fool us,
// and stay within the int32-sized buffer (word index <= n_elems-1).
__global__ void k_detect(const unsigned int* ei, const unsigned int* nb) {
    __shared__ int cnt;
    int t = threadIdx.x;
    if (t == 0) cnt = 0;
    __syncthreads();
    if (ei[2 * (t * 3900) + 1] != 0) atomicAdd(&cnt, 1);   // word idx < 2M
    __syncthreads();
    if (t == 0) { g_is64e = (cnt == 0); cnt = 0; }
    __syncthreads();
    if (nb[2 * (t * 97) + 1] != 0) atomicAdd(&cnt, 1);     // word idx < 100k
    __syncthreads();
    if (t == 0) g_is64n = (cnt == 0);
}

__global__ void k_zero() {
    int i = blockIdx.x * 256 + threadIdx.x;
    int stride = gridDim.x * 256;
    float4* s4 = (float4*)g_S;
    for (int k = i; k < NN * HD / 4; k += stride) s4[k] = make_float4(0.f, 0.f, 0.f, 0.f);
    for (int k = i; k < NN; k += stride) { g_W[k] = 0.f; g_C[k] = 0.f; }
}

__global__ void k_cvt_edges(const void* ei, const float* wts) {
    int is64 = g_is64e;
    const long long* e64 = (const long long*)ei;
    const int*       e32 = (const int*)ei;
    for (int e = blockIdx.x * 256 + threadIdx.x; e < NE; e += gridDim.x * 256) {
        int r, c;
        if (is64) { r = (int)e64[e]; c = (int)e64[NE + e]; }
        else      { r = e32[e];      c = e32[NE + e]; }
        g_row[e] = r; g_col[e] = c;
        atomicAdd(&g_W[c], wts[e]);
        atomicAdd(&g_C[c], 1.0f);
    }
}

__global__ void k_cvt_nodes(const void* nb) {
    int is64 = g_is64n;
    const long long* n64 = (const long long*)nb;
    const int*       n32 = (const int*)nb;
    for (int i = blockIdx.x * 256 + threadIdx.x; i < NN; i += gridDim.x * 256)
        g_nb[i] = is64 ? (int)n64[i] : n32[i];
}

// ------------------------- small precomputations ---------------------------
// M[a][j] = sum_k mw2[a][k] * uw1[64+k][j];  c2[j] = mb2 @ uw1[64:128]
// uu[g][j] = u[g] @ uw1[128:160] + ub1
__global__ void k_prep(const float* mw2, const float* uw1, const float* ub1,
                       const float* mb2, const float* u) {
    int b = blockIdx.x, t = threadIdx.x;
    if (b < 128) {
        float s = 0.f;
        for (int k = 0; k < 64; k++) s += mw2[b * 64 + k] * uw1[(64 + k) * 128 + t];
        g_M[b * 128 + t] = s;
    } else if (b == 128) {
        float s = 0.f;
        for (int k = 0; k < 64; k++) s += mb2[k] * uw1[(64 + k) * 128 + t];
        g_c2[t] = s;
    } else {
        int g = b - 129;
        float s = ub1[t];
        for (int k = 0; k < 32; k++) s += u[g * 32 + k] * uw1[(128 + k) * 128 + t];
        g_uu[g * 128 + t] = s;
    }
}

// --------------------- xa = x @ mw1[0:64] + mb1  ---------------------------
// 128 rows x 128 cols per block, 256 threads, 8x8 per thread, K-tile 32.
__global__ void k_xa(const float* x, const float* mw1, const float* mb1) {
    __shared__ float As[128 * 33];
    __shared__ float Bs[32 * 128];
    int tid = threadIdx.x, tx = tid & 15, ty = tid >> 4;
    int row0 = blockIdx.x * 128;
    u64 acc[8][4];
#pragma unroll
    for (int i = 0; i < 8; i++)
#pragma unroll
        for (int j = 0; j < 4; j++) acc[i][j] = 0ull;

    for (int kt = 0; kt < 2; kt++) {
        for (int idx = tid; idx < 128 * 32; idx += 256) {
            int r = idx >> 5, k = idx & 31, gr = row0 + r;
            As[r * 33 + k] = (gr < NN) ? x[gr * 64 + kt * 32 + k] : 0.f;
        }
        for (int idx = tid; idx < 32 * 128; idx += 256)
            Bs[idx] = mw1[(kt * 32 + (idx >> 7)) * 128 + (idx & 127)];
        __syncthreads();
#pragma unroll 1
        for (int k = 0; k < 32; k++) {
            const u64* bp = (const u64*)&Bs[k * 128 + 8 * tx];
            u64 b0 = bp[0], b1 = bp[1], b2 = bp[2], b3 = bp[3];
#pragma unroll
            for (int i = 0; i < 8; i++) {
                u64 aa = pk2(As[(8 * ty + i) * 33 + k]);
                fma2(acc[i][0], aa, b0); fma2(acc[i][1], aa, b1);
                fma2(acc[i][2], aa, b2); fma2(acc[i][3], aa, b3);
            }
        }
        __syncthreads();
    }
#pragma unroll
    for (int i = 0; i < 8; i++) {
        int gr = row0 + 8 * ty + i;
        if (gr >= NN) break;
#pragma unroll
        for (int j = 0; j < 4; j++) {
            float lo, hi; up2(acc[i][j], lo, hi);
            int c = 8 * tx + 2 * j;
            float2 o; o.x = lo + mb1[c]; o.y = hi + mb1[c + 1];
            *(float2*)&g_xa[gr * 128 + c] = o;
        }
    }
}

// -------- edge kernel: h=relu(xa[row] + ea@mw1[64:96]); S += w*h -----------
__global__ void k_edge(const float* ea, const float* wts, const float* mw1) {
    __shared__ float As[128 * 33];
    __shared__ float Bs[32 * 128];
    int tid = threadIdx.x, tx = tid & 15, ty = tid >> 4;
    int e0 = blockIdx.x * 128;

    for (int idx = tid; idx < 32 * 128; idx += 256)
        Bs[idx] = mw1[(64 + (idx >> 7)) * 128 + (idx & 127)];
    for (int idx = tid; idx < 128 * 32; idx += 256) {
        int r = idx >> 5, k = idx & 31, ge = e0 + r;
        As[r * 33 + k] = (ge < NE) ? ea[ge * 32 + k] : 0.f;
    }
    __syncthreads();

    u64 acc[8][4];
#pragma unroll
    for (int i = 0; i < 8; i++)
#pragma unroll
        for (int j = 0; j < 4; j++) acc[i][j] = 0ull;
#pragma unroll 1
    for (int k = 0; k < 32; k++) {
        const u64* bp = (const u64*)&Bs[k * 128 + 8 * tx];
        u64 b0 = bp[0], b1 = bp[1], b2 = bp[2], b3 = bp[3];
#pragma unroll
        for (int i = 0; i < 8; i++) {
            u64 aa = pk2(As[(8 * ty + i) * 33 + k]);
            fma2(acc[i][0], aa, b0); fma2(acc[i][1], aa, b1);
            fma2(acc[i][2], aa, b2); fma2(acc[i][3], aa, b3);
        }
    }

#pragma unroll 1
    for (int i = 0; i < 8; i++) {
        int ge = e0 + 8 * ty + i;
        if (ge < NE) {
            int re = g_row[ge], ce = g_col[ge];
            float w = wts[ge];
            const float4* xr = (const float4*)&g_xa[re * 128 + 8 * tx];
            float4 x0 = xr[0], x1 = xr[1];
            float h[8];
            up2(acc[i][0], h[0], h[1]); up2(acc[i][1], h[2], h[3]);
            up2(acc[i][2], h[4], h[5]); up2(acc[i][3], h[6], h[7]);
            h[0] += x0.x; h[1] += x0.y; h[2] += x0.z; h[3] += x0.w;
            h[4] += x1.x; h[5] += x1.y; h[6] += x1.z; h[7] += x1.w;
#pragma unroll
            for (int j = 0; j < 8; j++) h[j] = fmaxf(h[j], 0.f) * w;
            float* sp = &g_S[ce * 128 + 8 * tx];
            red4(sp,     h[0], h[1], h[2], h[3]);
            red4(sp + 4, h[4], h[5], h[6], h[7]);
        }
    }
}

// ------ node kernel: h2 = relu([x, S/C] @ [uw1_x; M] + (W/C)c2 + uu[nb]) ---
__global__ void k_node(const float* x, const float* uw1) {
    __shared__ float As[128 * 33];
    __shared__ float Bs[32 * 128];
    __shared__ float sInv[128], sWC[128];
    int tid = threadIdx.x, tx = tid & 15, ty = tid >> 4;
    int n0 = blockIdx.x * 128;

    if (tid < 128) {
        int gn = n0 + tid;
        float c = (gn < NN) ? g_C[gn] : 1.f;
        float inv = 1.f / fmaxf(c, 1.f);
        sInv[tid] = inv;
        sWC[tid]  = (gn < NN) ? g_W[gn] * inv : 0.f;
    }
    __syncthreads();

    u64 acc[8][4];
#pragma unroll
    for (int i = 0; i < 8; i++)
#pragma unroll
        for (int j = 0; j < 4; j++) acc[i][j] = 0ull;

    for (int kt = 0; kt < 6; kt++) {
        int kb = kt * 32;
        for (int idx = tid; idx < 128 * 32; idx += 256) {
            int r = idx >> 5, k = idx & 31, gn = n0 + r, kk = kb + k;
            float v = 0.f;
            if (gn < NN) {
                if (kk < 64) v = x[gn * 64 + kk];
                else         v = g_S[gn * 128 + (kk - 64)] * sInv[r];
            }
            As[r * 33 + k] = v;
        }
        for (int idx = tid; idx < 32 * 128; idx += 256) {
            int k = idx >> 7, c = idx & 127, kk = kb + k;
            Bs[idx] = (kk < 64) ? uw1[kk * 128 + c] : g_M[(kk - 64) * 128 + c];
        }
        __syncthreads();
#pragma unroll 1
        for (int k = 0; k < 32; k++) {
            const u64* bp = (const u64*)&Bs[k * 128 + 8 * tx];
            u64 b0 = bp[0], b1 = bp[1], b2 = bp[2], b3 = bp[3];
#pragma unroll
            for (int i = 0; i < 8; i++) {
                u64 aa = pk2(As[(8 * ty + i) * 33 + k]);
                fma2(acc[i][0], aa, b0); fma2(acc[i][1], aa, b1);
                fma2(acc[i][2], aa, b2); fma2(acc[i][3], aa, b3);
            }
        }
        __syncthreads();
    }

#pragma unroll
    for (int i = 0; i < 8; i++) {
        int gn = n0 + 8 * ty + i;
        if (gn >= NN) break;
        int nbv = g_nb[gn];
        float wc = sWC[8 * ty + i];
#pragma unroll
        for (int j = 0; j < 4; j++) {
            float lo, hi; up2(acc[i][j], lo, hi);
            int c = 8 * tx + 2 * j;
            lo += wc * g_c2[c]     + g_uu[nbv * 128 + c];
            hi += wc * g_c2[c + 1] + g_uu[nbv * 128 + c + 1];
            float2 o; o.x = fmaxf(lo, 0.f); o.y = fmaxf(hi, 0.f);
            *(float2*)&g_h2[gn * 128 + c] = o;
        }
    }
}

// --------------------- out = h2 @ uw2 + ub2 (cols=64) ----------------------
__global__ void k_out(const float* uw2, const float* ub2, float* out) {
    __shared__ float As[128 * 33];
    __shared__ float Bs[32 * 64];
    int tid = threadIdx.x, tx = tid & 15, ty = tid >> 4;
    int n0 = blockIdx.x * 128;
    u64 acc[8][2];
#pragma unroll
    for (int i = 0; i < 8; i++) { acc[i][0] = 0ull; acc[i][1] = 0ull; }

    for (int kt = 0; kt < 4; kt++) {
        int kb = kt * 32;
        for (int idx = tid; idx < 128 * 32; idx += 256) {
            int r = idx >> 5, k = idx & 31, gn = n0 + r;
            As[r * 33 + k] = (gn < NN) ? g_h2[gn * 128 + kb + k] : 0.f;
        }
        for (int idx = tid; idx < 32 * 64; idx += 256)
            Bs[idx] = uw2[(kb + (idx >> 6)) * 64 + (idx & 63)];
        __syncthreads();
#pragma unroll 1
        for (int k = 0; k < 32; k++) {
            const u64* bp = (const u64*)&Bs[k * 64 + 4 * tx];
            u64 b0 = bp[0], b1 = bp[1];
#pragma unroll
            for (int i = 0; i < 8; i++) {
                u64 aa = pk2(As[(8 * ty + i) * 33 + k]);
                fma2(acc[i][0], aa, b0); fma2(acc[i][1], aa, b1);
            }
        }
        __syncthreads();
    }
#pragma unroll
    for (int i = 0; i < 8; i++) {
        int gn = n0 + 8 * ty + i;
        if (gn >= NN) break;
#pragma unroll
        for (int j = 0; j < 2; j++) {
            float lo, hi; up2(acc[i][j], lo, hi);
            int c = 4 * tx + 2 * j;
            float2 o; o.x = lo + ub2[c]; o.y = hi + ub2[c + 1];
            *(float2*)&out[gn * 64 + c] = o;
        }
    }
}

// ------------------------------- launch ------------------------------------
extern "C" void kernel_launch(void* const* d_in, const int* in_sizes, int n_in,
                              void* d_out, int out_size) {
    const float* x    = (const float*)d_in[0];
    const void*  ei   = d_in[1];
    const float* ea   = (const float*)d_in[2];
    const float* u    = (const float*)d_in[3];
    const void*  nb   = d_in[4];
    const float* wts  = (const float*)d_in[5];
    const float* mw1  = (const float*)d_in[6];
    const float* mb1  = (const float*)d_in[7];
    const float* mw2  = (const float*)d_in[8];
    const float* mb2  = (const float*)d_in[9];
    const float* uw1  = (const float*)d_in[10];
    const float* ub1  = (const float*)d_in[11];
    const float* uw2  = (const float*)d_in[12];
    const float* ub2  = (const float*)d_in[13];
    float* out = (float*)d_out;

    k_detect<<<1, 256>>>((const unsigned int*)ei, (const unsigned int*)nb);
    k_zero<<<2048, 256>>>();
    k_cvt_edges<<<2048, 256>>>(ei, wts);
    k_cvt_nodes<<<256, 256>>>(nb);
    k_prep<<<193, 128>>>(mw2, uw1, ub1, mb2, u);
    k_xa<<<(NN + 127) / 128, 256>>>(x, mw1, mb1);
    k_edge<<<(NE + 127) / 128, 256>>>(ea, wts, mw1);
    k_node<<<(NN + 127) / 128, 256>>>(x, uw1);
    k_out<<<(NN + 127) / 128, 256>>>(uw2, ub2, out);
}